// round 4
// baseline (speedup 1.0000x reference)
#include <cuda_runtime.h>
#include <cuda_bf16.h>
#include <cuda_pipeline.h>
#include <cstdint>

// OverlapPatchEmbed: x (B=64, C=3, H=224, W=224) f32 -> out (B, 729, C, 256) f32
// out[b][pi*27+pj][c][r*16+s] = x[b][c][pi*8+r][pj*8+s]
//
// Block = (b, pi); loop over c with cp.async double-buffering:
// prefetch band (c+1) into buf[(c+1)&1] while storing band c from buf[c&1].
// Load side: contiguous 14336B via LDGSTS.128 (async, register-free).
// Store side: fully coalesced STG.128; smem pitch 240 floats -> conflict-free LDS.128.

namespace {
constexpr int B  = 64;
constexpr int C  = 3;
constexpr int H  = 224;
constexpr int W  = 224;
constexpr int N  = 27;
constexpr int TPB = 256;

constexpr int W4      = W / 4;       // 56 float4 per input row
constexpr int ROWS    = 16;
constexpr int LOAD_V  = ROWS * W4;   // 896 float4 per band
constexpr int PITCH4  = 60;          // 240-float pitch (mod 32 == 16): conflict-free
constexpr int STORE_V = N * 64;      // 1728 float4 per band-channel
constexpr int NBLOCKS = B * N;       // 1728
}

__global__ __launch_bounds__(TPB)
void overlap_patch_kernel(const float4* __restrict__ x, float4* __restrict__ out)
{
    __shared__ float4 s[2][ROWS * PITCH4];   // 2 x 15360 B

    const int bx  = blockIdx.x;
    const int pi  = bx % N;
    const int b   = bx / N;
    const int tid = threadIdx.x;

    // gmem float4 base of band (b, c, pi): channel stride = H*W4
    const int band0 = (b * C * H + pi * 8) * W4;

    // prefetch channel 0
    #pragma unroll
    for (int k = 0; k < 4; k++) {
        int i = tid + k * TPB;
        if (i < LOAD_V) {
            int row = i / W4;
            int col = i - row * W4;
            __pipeline_memcpy_async(&s[0][row * PITCH4 + col], &x[band0 + i], 16);
        }
    }
    __pipeline_commit();

    #pragma unroll
    for (int c = 0; c < C; c++) {
        if (c + 1 < C) {
            const int nb = band0 + (c + 1) * H * W4;
            #pragma unroll
            for (int k = 0; k < 4; k++) {
                int i = tid + k * TPB;
                if (i < LOAD_V) {
                    int row = i / W4;
                    int col = i - row * W4;
                    __pipeline_memcpy_async(&s[(c + 1) & 1][row * PITCH4 + col],
                                            &x[nb + i], 16);
                }
            }
            __pipeline_commit();
            __pipeline_wait_prior(1);
        } else {
            __pipeline_wait_prior(0);
        }
        __syncthreads();   // band c visible to all threads

        // store band c: out float4 index = ob0 + pj*(C*64) + q, q = r*4 + s4
        const int ob0 = ((b * (N * N) + pi * N) * C + c) * 64;
        const float4* sb = s[c & 1];
        #pragma unroll
        for (int k = 0; k < 7; k++) {
            int j = tid + k * TPB;
            if (j < STORE_V) {
                int pj = j >> 6;
                int q  = j & 63;
                int r  = q >> 2;
                int s4 = q & 3;
                out[ob0 + pj * (C * 64) + q] = sb[r * PITCH4 + pj * 2 + s4];
            }
        }
        __syncthreads();   // buffer c&1 free for reuse (prefetch c+2)
    }
}

extern "C" void kernel_launch(void* const* d_in, const int* in_sizes, int n_in,
                              void* d_out, int out_size)
{
    const float4* x = (const float4*)d_in[0];
    float4* out = (float4*)d_out;
    overlap_patch_kernel<<<NBLOCKS, TPB>>>(x, out);
}

// round 5
// speedup vs baseline: 1.0215x; 1.0215x over previous
#include <cuda_runtime.h>
#include <cuda_bf16.h>
#include <cstdint>

// OverlapPatchEmbed: x (B=64, C=3, H=224, W=224) f32 -> out (B, 729, C, 256) f32
// out[b][pi*27+pj][c][r*16+s] = x[b][c][pi*8+r][pj*8+s]
//
// Smem-staged, block = (b, c, pi). Same structure as the 27.4us version, but
// both phases are explicitly register-batched: all LDGs issued before any STS,
// all LDSs issued before any STG -> per-thread MLP 4 (gmem) / 7 (smem),
// hiding latency instead of relying on occupancy.

namespace {
constexpr int B  = 64;
constexpr int C  = 3;
constexpr int H  = 224;
constexpr int W  = 224;   // 56 float4 per row
constexpr int N  = 27;
constexpr int TPB = 256;

constexpr int W4      = W / 4;          // 56 float4 per input row
constexpr int ROWS    = 16;
constexpr int LOAD_V  = ROWS * W4;      // 896 float4 per block
constexpr int PITCH4  = 60;             // 240-float pitch (mod 32 == 16): conflict-free
constexpr int STORE_V = N * 64;         // 1728 float4 per block
constexpr int NBLOCKS = B * C * N;      // 5184

constexpr int LK = 4;                   // ceil(896/256)
constexpr int SK = 7;                   // ceil(1728/256)
}

__global__ __launch_bounds__(TPB)
void overlap_patch_kernel(const float4* __restrict__ x, float4* __restrict__ out)
{
    __shared__ float4 s[ROWS * PITCH4];   // 15360 bytes

    const int bx  = blockIdx.x;
    const int pi  = bx % N;
    const int c   = (bx / N) % C;
    const int b   = bx / (N * C);
    const int tid = threadIdx.x;

    // ---- load phase: batch all LDGs, then all STSs ----
    const int in_base = ((b * C + c) * H + pi * 8) * W4;   // float4 index

    float4 lv[LK];
    #pragma unroll
    for (int k = 0; k < LK; k++) {
        int i = tid + k * TPB;
        if (i < LOAD_V) lv[k] = __ldg(&x[in_base + i]);
    }
    #pragma unroll
    for (int k = 0; k < LK; k++) {
        int i = tid + k * TPB;
        if (i < LOAD_V) {
            int row = i / W4;
            int col = i - row * W4;
            s[row * PITCH4 + col] = lv[k];
        }
    }
    __syncthreads();

    // ---- store phase: batch all LDSs, then all STGs ----
    const int ob0 = ((b * (N * N) + pi * N) * C + c) * 64;

    float4 sv[SK];
    #pragma unroll
    for (int k = 0; k < SK; k++) {
        int j = tid + k * TPB;
        if (j < STORE_V) {
            int pj = j >> 6;
            int q  = j & 63;
            int r  = q >> 2;
            int s4 = q & 3;
            sv[k] = s[r * PITCH4 + pj * 2 + s4];
        }
    }
    #pragma unroll
    for (int k = 0; k < SK; k++) {
        int j = tid + k * TPB;
        if (j < STORE_V) {
            int pj = j >> 6;
            int q  = j & 63;
            out[ob0 + pj * (C * 64) + q] = sv[k];
        }
    }
}

extern "C" void kernel_launch(void* const* d_in, const int* in_sizes, int n_in,
                              void* d_out, int out_size)
{
    const float4* x = (const float4*)d_in[0];
    float4* out = (float4*)d_out;
    overlap_patch_kernel<<<NBLOCKS, TPB>>>(x, out);
}